// round 7
// baseline (speedup 1.0000x reference)
#include <cuda_runtime.h>
#include <cuda_bf16.h>
#include <cstdint>

// MultiHeadAttentionMap: B=2, S=2048, D=1024, H=16, head_dim=64
// R7: HMMA bf16 FA; double-buffered smem (1 barrier/iter), hoisted LDG prefetch,
//     streamed P conversion (reg pressure), paired-nt GEMM1 chains.

#define S_LEN 2048
#define DMODEL 1024
#define NHEAD 16
#define BATCH 2
#define HD 64
#define BM 128
#define BN 64
#define NKT (S_LEN / BN)
#define NTH 128

#define ROWB 144
#define TILE_B (64 * ROWB)      // 9216
#define BUF_B  (4 * TILE_B)     // 36864 per buffer (KH,KL,VH,VL)
#define SMEM_TOTAL (2 * BUF_B)  // 73728

__device__ __align__(8) unsigned g_mbits[BATCH * S_LEN * S_LEN / 32];

__device__ __forceinline__ uint32_t smem_u32(const void* p) {
    uint32_t a;
    asm("{ .reg .u64 t; cvta.to.shared.u64 t, %1; cvt.u32.u64 %0, t; }" : "=r"(a) : "l"(p));
    return a;
}
__device__ __forceinline__ uint32_t pack2(float lo, float hi) {
    uint32_t d;
    asm("cvt.rn.bf16x2.f32 %0, %1, %2;" : "=r"(d) : "f"(hi), "f"(lo));
    return d;
}
__device__ __forceinline__ float tobf(float f) {
    return __bfloat162float(__float2bfloat16_rn(f));
}
__device__ __forceinline__ void mma_bf16(float* c, const uint32_t* a, uint32_t b0, uint32_t b1) {
    asm volatile(
        "mma.sync.aligned.m16n8k16.row.col.f32.bf16.bf16.f32 "
        "{%0,%1,%2,%3}, {%4,%5,%6,%7}, {%8,%9}, {%0,%1,%2,%3};"
        : "+f"(c[0]), "+f"(c[1]), "+f"(c[2]), "+f"(c[3])
        : "r"(a[0]), "r"(a[1]), "r"(a[2]), "r"(a[3]), "r"(b0), "r"(b1));
}
__device__ __forceinline__ void ldsm_x4(uint32_t* r, uint32_t addr) {
    asm volatile("ldmatrix.sync.aligned.m8n8.x4.shared.b16 {%0,%1,%2,%3}, [%4];"
        : "=r"(r[0]), "=r"(r[1]), "=r"(r[2]), "=r"(r[3]) : "r"(addr));
}
__device__ __forceinline__ void ldsm_x4_t(uint32_t* r, uint32_t addr) {
    asm volatile("ldmatrix.sync.aligned.m8n8.x4.trans.shared.b16 {%0,%1,%2,%3}, [%4];"
        : "=r"(r[0]), "=r"(r[1]), "=r"(r[2]), "=r"(r[3]) : "r"(addr));
}
__device__ __forceinline__ void cvt_sts(char* pH, char* pL, uint32_t so, float4 t) {
    float h0 = tobf(t.x), h1 = tobf(t.y), h2 = tobf(t.z), h3 = tobf(t.w);
    *(uint2*)(pH + so) = make_uint2(pack2(h0, h1), pack2(h2, h3));
    *(uint2*)(pL + so) = make_uint2(pack2(t.x - h0, t.y - h1), pack2(t.z - h2, t.w - h3));
}

// ---------------- mask bit-packing ----------------
__global__ void pack_mask(const int* __restrict__ mask) {
    int idx = blockIdx.x * 256 + threadIdx.x;
    int val = mask[idx] != 0;
    unsigned bb = __ballot_sync(0xffffffffu, val);
    if ((threadIdx.x & 31) == 0) g_mbits[idx >> 5] = bb;
}

// ---------------- main kernel ----------------
__global__ void __launch_bounds__(NTH, 2)
mha_mma(const float* __restrict__ Q, const float* __restrict__ K,
        const float* __restrict__ V, float* __restrict__ Out)
{
    extern __shared__ __align__(16) char sm[];

    const int tid  = threadIdx.x;
    const int lane = tid & 31;
    const int wid  = tid >> 5;
    const int g    = lane >> 2;
    const int tig  = lane & 3;
    const int qt = blockIdx.x, h = blockIdx.y, b = blockIdx.z;
    const int q0 = qt * BM;
    const int wr = wid * 32;

    int rowg[2][2];
    rowg[0][0] = q0 + wr + g;      rowg[0][1] = rowg[0][0] + 8;
    rowg[1][0] = rowg[0][0] + 16;  rowg[1][1] = rowg[0][0] + 24;

    // per-thread load-unit coords (8 units per matrix)
    const int lrow = tid >> 4;              // 0..7 (+8 per unit)
    const int lc4  = (tid & 15) << 2;       // float col
    const uint32_t lso = (uint32_t)(lrow * ROWB + lc4 * 2);

    // ---- Q fragments (persistent, pre-scaled by 1/8), split hi/lo ----
    uint32_t qh[2][4][4], ql[2][4][4];
    {
        const float* qp = Q + ((size_t)b * S_LEN) * DMODEL + h * HD;
        #pragma unroll
        for (int rs = 0; rs < 2; rs++)
            #pragma unroll
            for (int ks = 0; ks < 4; ks++) {
                int c0 = ks * 16 + 2 * tig;
                #pragma unroll
                for (int fi = 0; fi < 4; fi++) {
                    int rrow = rowg[rs][fi & 1];
                    int ccol = c0 + ((fi & 2) ? 8 : 0);
                    float2 t = *(const float2*)(qp + (size_t)rrow * DMODEL + ccol);
                    t.x *= 0.125f; t.y *= 0.125f;
                    float h0 = tobf(t.x), h1 = tobf(t.y);
                    qh[rs][ks][fi] = pack2(h0, h1);
                    ql[rs][ks][fi] = pack2(t.x - h0, t.y - h1);
                }
            }
    }

    float o[2][8][4];
    #pragma unroll
    for (int rs = 0; rs < 2; rs++)
        #pragma unroll
        for (int dt = 0; dt < 8; dt++)
            #pragma unroll
            for (int j = 0; j < 4; j++) o[rs][dt][j] = 0.f;
    float m_i[2][2] = {{-1e30f, -1e30f}, {-1e30f, -1e30f}};
    float l_i[2][2] = {{0.f, 0.f}, {0.f, 0.f}};

    const float* kp = K + ((size_t)b * S_LEN) * DMODEL + h * HD;
    const float* vp = V + ((size_t)b * S_LEN) * DMODEL + h * HD;
    const unsigned long long* mb64 = (const unsigned long long*)g_mbits;
    size_t mrow[2][2];
    #pragma unroll
    for (int rs = 0; rs < 2; rs++) {
        mrow[rs][0] = ((size_t)b * S_LEN + rowg[rs][0]) * 32;
        mrow[rs][1] = ((size_t)b * S_LEN + rowg[rs][1]) * 32;
    }

    const int krow = lane & 7;
    const int kq   = lane >> 3;

    // ---- prologue: load tile 0 into buffer 0 ----
    {
        char* pKH = sm;            char* pKL = sm + TILE_B;
        char* pVH = sm + 2*TILE_B; char* pVL = sm + 3*TILE_B;
        #pragma unroll
        for (int u = 0; u < 8; ++u) {
            int row = lrow + u * 8;
            uint32_t so = lso + (uint32_t)(u * 8 * ROWB);
            cvt_sts(pKH, pKL, so, *(const float4*)(kp + (size_t)row * DMODEL + lc4));
            cvt_sts(pVH, pVL, so, *(const float4*)(vp + (size_t)row * DMODEL + lc4));
        }
    }
    __syncthreads();

    for (int kt = 0; kt < NKT; ++kt) {
        char* cb = sm + (kt & 1) * BUF_B;
        char* nb = sm + ((kt + 1) & 1) * BUF_B;
        const uint32_t sKH = smem_u32(cb);
        const uint32_t sVH = sKH + 2 * TILE_B;
        const bool pf = (kt + 1) < NKT;
        const int nk0 = (kt + 1) * BN;

        // ---- issue K LDGs for next tile (land during GEMM1) ----
        float4 ldk[8];
        if (pf) {
            #pragma unroll
            for (int u = 0; u < 8; ++u)
                ldk[u] = *(const float4*)(kp + (size_t)(nk0 + lrow + u * 8) * DMODEL + lc4);
        }

        // ---- GEMM1: S = QhKh + QhKl + QlKh (nt pairs -> 4 chains) ----
        float s[2][8][4];
        #pragma unroll
        for (int rs = 0; rs < 2; rs++)
            #pragma unroll
            for (int nt = 0; nt < 8; nt++)
                #pragma unroll
                for (int j = 0; j < 4; j++) s[rs][nt][j] = 0.f;

        #pragma unroll
        for (int kpair = 0; kpair < 2; kpair++) {
            #pragma unroll
            for (int ntp = 0; ntp < 4; ntp++) {
                const int nt0 = 2 * ntp, nt1 = 2 * ntp + 1;
                uint32_t a0 = (uint32_t)((nt0 * 8 + krow) * ROWB + (kpair * 32 + kq * 8) * 2);
                uint32_t a1 = (uint32_t)((nt1 * 8 + krow) * ROWB + (kpair * 32 + kq * 8) * 2);
                uint32_t bh0[4], bl0[4], bh1[4], bl1[4];
                ldsm_x4(bh0, sKH + a0);
                ldsm_x4(bl0, sKH + TILE_B + a0);
                ldsm_x4(bh1, sKH + a1);
                ldsm_x4(bl1, sKH + TILE_B + a1);
                #pragma unroll
                for (int rs = 0; rs < 2; rs++) {
                    mma_bf16(s[rs][nt0], qh[rs][2*kpair],   bh0[0], bh0[1]);
                    mma_bf16(s[rs][nt1], qh[rs][2*kpair],   bh1[0], bh1[1]);
                    mma_bf16(s[rs][nt0], qh[rs][2*kpair],   bl0[0], bl0[1]);
                    mma_bf16(s[rs][nt1], qh[rs][2*kpair],   bl1[0], bl1[1]);
                    mma_bf16(s[rs][nt0], ql[rs][2*kpair],   bh0[0], bh0[1]);
                    mma_bf16(s[rs][nt1], ql[rs][2*kpair],   bh1[0], bh1[1]);
                    mma_bf16(s[rs][nt0], qh[rs][2*kpair+1], bh0[2], bh0[3]);
                    mma_bf16(s[rs][nt1], qh[rs][2*kpair+1], bh1[2], bh1[3]);
                    mma_bf16(s[rs][nt0], qh[rs][2*kpair+1], bl0[2], bl0[3]);
                    mma_bf16(s[rs][nt1], qh[rs][2*kpair+1], bl1[2], bl1[3]);
                    mma_bf16(s[rs][nt0], ql[rs][2*kpair+1], bh0[2], bh0[3]);
                    mma_bf16(s[rs][nt1], ql[rs][2*kpair+1], bh1[2], bh1[3]);
                }
            }
        }

        // ---- store next-K, then issue V LDGs (land during softmax+GEMM2) ----
        if (pf) {
            #pragma unroll
            for (int u = 0; u < 8; ++u)
                cvt_sts(nb, nb + TILE_B, lso + (uint32_t)(u * 8 * ROWB), ldk[u]);
        }
        float4 ldv[8];
        if (pf) {
            #pragma unroll
            for (int u = 0; u < 8; ++u)
                ldv[u] = *(const float4*)(vp + (size_t)(nk0 + lrow + u * 8) * DMODEL + lc4);
        }

        // ---- mask + online softmax ----
        #pragma unroll
        for (int rs = 0; rs < 2; rs++) {
            unsigned long long mb0 = mb64[mrow[rs][0] + kt];
            unsigned long long mb1 = mb64[mrow[rs][1] + kt];
            if ((mb0 & mb1) != ~0ull) {
                #pragma unroll
                for (int nt = 0; nt < 8; nt++) {
                    int c0 = nt * 8 + 2 * tig;
                    s[rs][nt][0] += ((mb0 >> c0) & 1ull) ? 0.f : -1.0e9f;
                    s[rs][nt][1] += ((mb0 >> (c0+1)) & 1ull) ? 0.f : -1.0e9f;
                    s[rs][nt][2] += ((mb1 >> c0) & 1ull) ? 0.f : -1.0e9f;
                    s[rs][nt][3] += ((mb1 >> (c0+1)) & 1ull) ? 0.f : -1.0e9f;
                }
            }
            float mx0 = -1e30f, mx1 = -1e30f;
            #pragma unroll
            for (int nt = 0; nt < 8; nt++) {
                mx0 = fmaxf(mx0, fmaxf(s[rs][nt][0], s[rs][nt][1]));
                mx1 = fmaxf(mx1, fmaxf(s[rs][nt][2], s[rs][nt][3]));
            }
            mx0 = fmaxf(mx0, __shfl_xor_sync(0xffffffffu, mx0, 1));
            mx0 = fmaxf(mx0, __shfl_xor_sync(0xffffffffu, mx0, 2));
            mx1 = fmaxf(mx1, __shfl_xor_sync(0xffffffffu, mx1, 1));
            mx1 = fmaxf(mx1, __shfl_xor_sync(0xffffffffu, mx1, 2));

            float mn0 = fmaxf(m_i[rs][0], mx0), mn1 = fmaxf(m_i[rs][1], mx1);
            float a0 = __expf(m_i[rs][0] - mn0), a1 = __expf(m_i[rs][1] - mn1);
            float sum0 = 0.f, sum1 = 0.f;
            #pragma unroll
            for (int nt = 0; nt < 8; nt++) {
                s[rs][nt][0] = __expf(s[rs][nt][0] - mn0);
                s[rs][nt][1] = __expf(s[rs][nt][1] - mn0);
                s[rs][nt][2] = __expf(s[rs][nt][2] - mn1);
                s[rs][nt][3] = __expf(s[rs][nt][3] - mn1);
                sum0 += s[rs][nt][0] + s[rs][nt][1];
                sum1 += s[rs][nt][2] + s[rs][nt][3];
            }
            sum0 += __shfl_xor_sync(0xffffffffu, sum0, 1);
            sum0 += __shfl_xor_sync(0xffffffffu, sum0, 2);
            sum1 += __shfl_xor_sync(0xffffffffu, sum1, 1);
            sum1 += __shfl_xor_sync(0xffffffffu, sum1, 2);
            l_i[rs][0] = l_i[rs][0] * a0 + sum0;  m_i[rs][0] = mn0;
            l_i[rs][1] = l_i[rs][1] * a1 + sum1;  m_i[rs][1] = mn1;
            #pragma unroll
            for (int dt = 0; dt < 8; dt++) {
                o[rs][dt][0] *= a0; o[rs][dt][1] *= a0;
                o[rs][dt][2] *= a1; o[rs][dt][3] *= a1;
            }
        }

        // ---- GEMM2: O += PhVh + PhVl + PlVh (streamed P conversion) ----
        #pragma unroll
        for (int kpair = 0; kpair < 2; kpair++) {
            uint32_t ph2[2][2][4], pl2[2][2][4];
            #pragma unroll
            for (int rs = 0; rs < 2; rs++)
                #pragma unroll
                for (int i = 0; i < 2; i++) {
                    const int ntA = 4 * kpair + 2 * i, ntB = ntA + 1;
                    float p00 = s[rs][ntA][0], p01 = s[rs][ntA][1];
                    float p10 = s[rs][ntA][2], p11 = s[rs][ntA][3];
                    float p20 = s[rs][ntB][0], p21 = s[rs][ntB][1];
                    float p30 = s[rs][ntB][2], p31 = s[rs][ntB][3];
                    float h00 = tobf(p00), h01 = tobf(p01), h10 = tobf(p10), h11 = tobf(p11);
                    float h20 = tobf(p20), h21 = tobf(p21), h30 = tobf(p30), h31 = tobf(p31);
                    ph2[rs][i][0] = pack2(h00, h01); ph2[rs][i][1] = pack2(h10, h11);
                    ph2[rs][i][2] = pack2(h20, h21); ph2[rs][i][3] = pack2(h30, h31);
                    pl2[rs][i][0] = pack2(p00-h00, p01-h01); pl2[rs][i][1] = pack2(p10-h10, p11-h11);
                    pl2[rs][i][2] = pack2(p20-h20, p21-h21); pl2[rs][i][3] = pack2(p30-h30, p31-h31);
                }
            #pragma unroll
            for (int dt = 0; dt < 8; dt++) {
                uint32_t aoff = (uint32_t)((kpair * 32 + lane) * ROWB + dt * 16);
                uint32_t vh[4], vl[4];
                ldsm_x4_t(vh, sVH + aoff);
                ldsm_x4_t(vl, sVH + TILE_B + aoff);
                #pragma unroll
                for (int rs = 0; rs < 2; rs++) {
                    mma_bf16(o[rs][dt], ph2[rs][0], vh[0], vh[1]);
                    mma_bf16(o[rs][dt], ph2[rs][0], vl[0], vl[1]);
                    mma_bf16(o[rs][dt], pl2[rs][0], vh[0], vh[1]);
                    mma_bf16(o[rs][dt], ph2[rs][1], vh[2], vh[3]);
                    mma_bf16(o[rs][dt], ph2[rs][1], vl[2], vl[3]);
                    mma_bf16(o[rs][dt], pl2[rs][1], vh[2], vh[3]);
                }
            }
        }

        // ---- store next-V, barrier ----
        if (pf) {
            #pragma unroll
            for (int u = 0; u < 8; ++u)
                cvt_sts(nb + 2 * TILE_B, nb + 3 * TILE_B, lso + (uint32_t)(u * 8 * ROWB), ldv[u]);
        }
        __syncthreads();
    }

    // ---- normalize + write out ----
    #pragma unroll
    for (int rs = 0; rs < 2; rs++) {
        float inv0 = 1.f / l_i[rs][0], inv1 = 1.f / l_i[rs][1];
        float* op0 = Out + ((size_t)b * S_LEN + rowg[rs][0]) * DMODEL + h * HD;
        float* op1 = Out + ((size_t)b * S_LEN + rowg[rs][1]) * DMODEL + h * HD;
        #pragma unroll
        for (int dt = 0; dt < 8; dt++) {
            int c0 = dt * 8 + 2 * tig;
            *(float2*)(op0 + c0) = make_float2(o[rs][dt][0] * inv0, o[rs][dt][1] * inv0);
            *(float2*)(op1 + c0) = make_float2(o[rs][dt][2] * inv1, o[rs][dt][3] * inv1);
        }
    }
}

extern "C" void kernel_launch(void* const* d_in, const int* in_sizes, int n_in,
                              void* d_out, int out_size)
{
    const float* q = (const float*)d_in[0];
    const float* k = (const float*)d_in[1];
    const float* v = (const float*)d_in[2];
    const int* mask = (const int*)d_in[3];
    float* out = (float*)d_out;

    pack_mask<<<BATCH * S_LEN * S_LEN / 256, 256>>>(mask);

    cudaFuncSetAttribute(mha_mma, cudaFuncAttributeMaxDynamicSharedMemorySize, SMEM_TOTAL);
    dim3 grid(S_LEN / BM, NHEAD, BATCH);
    mha_mma<<<grid, NTH, SMEM_TOTAL>>>(q, k, v, out);
}

// round 8
// speedup vs baseline: 1.1925x; 1.1925x over previous
#include <cuda_runtime.h>
#include <cuda_bf16.h>
#include <cstdint>

// MultiHeadAttentionMap: B=2, S=2048, D=1024, H=16, head_dim=64
// R8: HMMA bf16 FA. Q in smem (ldsm per k-pair), streamed P conversion,
//     single K/V buffer, 2 barriers/iter. Goal: kill register spills.

#define S_LEN 2048
#define DMODEL 1024
#define NHEAD 16
#define BATCH 2
#define HD 64
#define BM 128
#define BN 64
#define NKT (S_LEN / BN)
#define NTH 128

#define ROWB 144
#define TILE_B (64 * ROWB)       // 9216  (64-row tile)
#define QTILE_B (128 * ROWB)     // 18432 (128-row Q tile)
// layout: KH | KL | VH | VL | QH | QL
#define OFF_KH 0
#define OFF_KL TILE_B
#define OFF_VH (2 * TILE_B)
#define OFF_VL (3 * TILE_B)
#define OFF_QH (4 * TILE_B)
#define OFF_QL (4 * TILE_B + QTILE_B)
#define SMEM_TOTAL (4 * TILE_B + 2 * QTILE_B)   // 73728

__device__ __align__(8) unsigned g_mbits[BATCH * S_LEN * S_LEN / 32];

__device__ __forceinline__ uint32_t smem_u32(const void* p) {
    uint32_t a;
    asm("{ .reg .u64 t; cvta.to.shared.u64 t, %1; cvt.u32.u64 %0, t; }" : "=r"(a) : "l"(p));
    return a;
}
__device__ __forceinline__ uint32_t pack2(float lo, float hi) {
    uint32_t d;
    asm("cvt.rn.bf16x2.f32 %0, %1, %2;" : "=r"(d) : "f"(hi), "f"(lo));
    return d;
}
__device__ __forceinline__ float tobf(float f) {
    return __bfloat162float(__float2bfloat16_rn(f));
}
__device__ __forceinline__ void mma_bf16(float* c, const uint32_t* a, uint32_t b0, uint32_t b1) {
    asm volatile(
        "mma.sync.aligned.m16n8k16.row.col.f32.bf16.bf16.f32 "
        "{%0,%1,%2,%3}, {%4,%5,%6,%7}, {%8,%9}, {%0,%1,%2,%3};"
        : "+f"(c[0]), "+f"(c[1]), "+f"(c[2]), "+f"(c[3])
        : "r"(a[0]), "r"(a[1]), "r"(a[2]), "r"(a[3]), "r"(b0), "r"(b1));
}
__device__ __forceinline__ void ldsm_x4(uint32_t* r, uint32_t addr) {
    asm volatile("ldmatrix.sync.aligned.m8n8.x4.shared.b16 {%0,%1,%2,%3}, [%4];"
        : "=r"(r[0]), "=r"(r[1]), "=r"(r[2]), "=r"(r[3]) : "r"(addr));
}
__device__ __forceinline__ void ldsm_x4_t(uint32_t* r, uint32_t addr) {
    asm volatile("ldmatrix.sync.aligned.m8n8.x4.trans.shared.b16 {%0,%1,%2,%3}, [%4];"
        : "=r"(r[0]), "=r"(r[1]), "=r"(r[2]), "=r"(r[3]) : "r"(addr));
}
__device__ __forceinline__ void cvt_sts(char* pH, char* pL, uint32_t so, float4 t) {
    float h0 = tobf(t.x), h1 = tobf(t.y), h2 = tobf(t.z), h3 = tobf(t.w);
    *(uint2*)(pH + so) = make_uint2(pack2(h0, h1), pack2(h2, h3));
    *(uint2*)(pL + so) = make_uint2(pack2(t.x - h0, t.y - h1), pack2(t.z - h2, t.w - h3));
}

// ---------------- mask bit-packing ----------------
__global__ void pack_mask(const int* __restrict__ mask) {
    int idx = blockIdx.x * 256 + threadIdx.x;
    int val = mask[idx] != 0;
    unsigned bb = __ballot_sync(0xffffffffu, val);
    if ((threadIdx.x & 31) == 0) g_mbits[idx >> 5] = bb;
}

// ---------------- main kernel ----------------
__global__ void __launch_bounds__(NTH, 2)
mha_mma(const float* __restrict__ Q, const float* __restrict__ K,
        const float* __restrict__ V, float* __restrict__ Out)
{
    extern __shared__ __align__(16) char sm[];
    const uint32_t sbase = smem_u32(sm);

    const int tid  = threadIdx.x;
    const int lane = tid & 31;
    const int wid  = tid >> 5;
    const int g    = lane >> 2;
    const int tig  = lane & 3;
    const int qt = blockIdx.x, h = blockIdx.y, b = blockIdx.z;
    const int q0 = qt * BM;
    const int wr = wid * 32;

    int rowg[2][2];
    rowg[0][0] = q0 + wr + g;      rowg[0][1] = rowg[0][0] + 8;
    rowg[1][0] = rowg[0][0] + 16;  rowg[1][1] = rowg[0][0] + 24;

    // cooperative-load unit coords
    const int lrow = tid >> 4;              // 0..7
    const int lc4  = (tid & 15) << 2;
    const uint32_t lso = (uint32_t)(lrow * ROWB + lc4 * 2);

    // ---- prologue: Q (pre-scaled 1/8) -> smem hi/lo ----
    {
        const float* qp = Q + ((size_t)b * S_LEN + q0) * DMODEL + h * HD;
        #pragma unroll 4
        for (int u = 0; u < 16; ++u) {
            int idx = tid + u * NTH;
            int row = idx >> 4, c4 = (idx & 15) << 2;
            float4 t = *(const float4*)(qp + (size_t)row * DMODEL + c4);
            t.x *= 0.125f; t.y *= 0.125f; t.z *= 0.125f; t.w *= 0.125f;
            cvt_sts(sm + OFF_QH, sm + OFF_QL, (uint32_t)(row * ROWB + c4 * 2), t);
        }
    }

    float o[2][8][4];
    #pragma unroll
    for (int rs = 0; rs < 2; rs++)
        #pragma unroll
        for (int dt = 0; dt < 8; dt++)
            #pragma unroll
            for (int j = 0; j < 4; j++) o[rs][dt][j] = 0.f;
    float m_i[2][2] = {{-1e30f, -1e30f}, {-1e30f, -1e30f}};
    float l_i[2][2] = {{0.f, 0.f}, {0.f, 0.f}};

    const float* kp = K + ((size_t)b * S_LEN) * DMODEL + h * HD;
    const float* vp = V + ((size_t)b * S_LEN) * DMODEL + h * HD;
    const unsigned long long* mb64 = (const unsigned long long*)g_mbits;
    size_t mrow[2][2];
    #pragma unroll
    for (int rs = 0; rs < 2; rs++) {
        mrow[rs][0] = ((size_t)b * S_LEN + rowg[rs][0]) * 32;
        mrow[rs][1] = ((size_t)b * S_LEN + rowg[rs][1]) * 32;
    }

    const int krow = lane & 7;
    const int kq   = lane >> 3;
    // Q ldsm lane address parts: row = lane&15, col-chunk = (lane>>4)*8
    const uint32_t qlrow = (uint32_t)(lane & 15);
    const uint32_t qlcol = (uint32_t)((lane >> 4) * 8 * 2);   // bytes

    for (int kt = 0; kt < NKT; ++kt) {
        const int k0 = kt * BN;
        __syncthreads();   // previous tile's fragment reads done

        // ---- cooperative load K,V tile: fp32 -> split bf16 -> smem ----
        #pragma unroll 4
        for (int u = 0; u < 8; ++u) {
            int row = lrow + u * 8;
            uint32_t so = lso + (uint32_t)(u * 8 * ROWB);
            cvt_sts(sm + OFF_KH, sm + OFF_KL, so,
                    *(const float4*)(kp + (size_t)(k0 + row) * DMODEL + lc4));
            cvt_sts(sm + OFF_VH, sm + OFF_VL, so,
                    *(const float4*)(vp + (size_t)(k0 + row) * DMODEL + lc4));
        }
        __syncthreads();

        // ---- GEMM1: S = QhKh + QhKl + QlKh (Q frags via ldsm per kpair) ----
        float s[2][8][4];
        #pragma unroll
        for (int rs = 0; rs < 2; rs++)
            #pragma unroll
            for (int nt = 0; nt < 8; nt++)
                #pragma unroll
                for (int j = 0; j < 4; j++) s[rs][nt][j] = 0.f;

        #pragma unroll
        for (int kpair = 0; kpair < 2; kpair++) {
            // load Q fragments for chunks 2*kpair, 2*kpair+1, both row-sets
            uint32_t qh2[2][2][4], ql2[2][2][4];
            #pragma unroll
            for (int rs = 0; rs < 2; rs++)
                #pragma unroll
                for (int c = 0; c < 2; c++) {
                    uint32_t qoff = (uint32_t)((wr + rs * 16 + qlrow) * ROWB)
                                  + (uint32_t)((2 * kpair + c) * 32) + qlcol;
                    ldsm_x4(qh2[rs][c], sbase + OFF_QH + qoff);
                    ldsm_x4(ql2[rs][c], sbase + OFF_QL + qoff);
                }
            #pragma unroll
            for (int ntp = 0; ntp < 4; ntp++) {
                const int nt0 = 2 * ntp, nt1 = 2 * ntp + 1;
                uint32_t a0 = (uint32_t)((nt0 * 8 + krow) * ROWB + (kpair * 32 + kq * 8) * 2);
                uint32_t a1 = (uint32_t)((nt1 * 8 + krow) * ROWB + (kpair * 32 + kq * 8) * 2);
                uint32_t bh0[4], bl0[4], bh1[4], bl1[4];
                ldsm_x4(bh0, sbase + OFF_KH + a0);
                ldsm_x4(bl0, sbase + OFF_KL + a0);
                ldsm_x4(bh1, sbase + OFF_KH + a1);
                ldsm_x4(bl1, sbase + OFF_KL + a1);
                #pragma unroll
                for (int rs = 0; rs < 2; rs++) {
                    mma_bf16(s[rs][nt0], qh2[rs][0], bh0[0], bh0[1]);
                    mma_bf16(s[rs][nt1], qh2[rs][0], bh1[0], bh1[1]);
                    mma_bf16(s[rs][nt0], qh2[rs][0], bl0[0], bl0[1]);
                    mma_bf16(s[rs][nt1], qh2[rs][0], bl1[0], bl1[1]);
                    mma_bf16(s[rs][nt0], ql2[rs][0], bh0[0], bh0[1]);
                    mma_bf16(s[rs][nt1], ql2[rs][0], bh1[0], bh1[1]);
                    mma_bf16(s[rs][nt0], qh2[rs][1], bh0[2], bh0[3]);
                    mma_bf16(s[rs][nt1], qh2[rs][1], bh1[2], bh1[3]);
                    mma_bf16(s[rs][nt0], qh2[rs][1], bl0[2], bl0[3]);
                    mma_bf16(s[rs][nt1], qh2[rs][1], bl1[2], bl1[3]);
                    mma_bf16(s[rs][nt0], ql2[rs][1], bh0[2], bh0[3]);
                    mma_bf16(s[rs][nt1], ql2[rs][1], bh1[2], bh1[3]);
                }
            }
        }

        // ---- mask + online softmax ----
        #pragma unroll
        for (int rs = 0; rs < 2; rs++) {
            unsigned long long mb0 = mb64[mrow[rs][0] + kt];
            unsigned long long mb1 = mb64[mrow[rs][1] + kt];
            if ((mb0 & mb1) != ~0ull) {
                #pragma unroll
                for (int nt = 0; nt < 8; nt++) {
                    int c0 = nt * 8 + 2 * tig;
                    s[rs][nt][0] += ((mb0 >> c0) & 1ull) ? 0.f : -1.0e9f;
                    s[rs][nt][1] += ((mb0 >> (c0+1)) & 1ull) ? 0.f : -1.0e9f;
                    s[rs][nt][2] += ((mb1 >> c0) & 1ull) ? 0.f : -1.0e9f;
                    s[rs][nt][3] += ((mb1 >> (c0+1)) & 1ull) ? 0.f : -1.0e9f;
                }
            }
            float mx0 = -1e30f, mx1 = -1e30f;
            #pragma unroll
            for (int nt = 0; nt < 8; nt++) {
                mx0 = fmaxf(mx0, fmaxf(s[rs][nt][0], s[rs][nt][1]));
                mx1 = fmaxf(mx1, fmaxf(s[rs][nt][2], s[rs][nt][3]));
            }
            mx0 = fmaxf(mx0, __shfl_xor_sync(0xffffffffu, mx0, 1));
            mx0 = fmaxf(mx0, __shfl_xor_sync(0xffffffffu, mx0, 2));
            mx1 = fmaxf(mx1, __shfl_xor_sync(0xffffffffu, mx1, 1));
            mx1 = fmaxf(mx1, __shfl_xor_sync(0xffffffffu, mx1, 2));

            float mn0 = fmaxf(m_i[rs][0], mx0), mn1 = fmaxf(m_i[rs][1], mx1);
            float a0 = __expf(m_i[rs][0] - mn0), a1 = __expf(m_i[rs][1] - mn1);
            float sum0 = 0.f, sum1 = 0.f;
            #pragma unroll
            for (int nt = 0; nt < 8; nt++) {
                s[rs][nt][0] = __expf(s[rs][nt][0] - mn0);
                s[rs][nt][1] = __expf(s[rs][nt][1] - mn0);
                s[rs][nt][2] = __expf(s[rs][nt][2] - mn1);
                s[rs][nt][3] = __expf(s[rs][nt][3] - mn1);
                sum0 += s[rs][nt][0] + s[rs][nt][1];
                sum1 += s[rs][nt][2] + s[rs][nt][3];
            }
            sum0 += __shfl_xor_sync(0xffffffffu, sum0, 1);
            sum0 += __shfl_xor_sync(0xffffffffu, sum0, 2);
            sum1 += __shfl_xor_sync(0xffffffffu, sum1, 1);
            sum1 += __shfl_xor_sync(0xffffffffu, sum1, 2);
            l_i[rs][0] = l_i[rs][0] * a0 + sum0;  m_i[rs][0] = mn0;
            l_i[rs][1] = l_i[rs][1] * a1 + sum1;  m_i[rs][1] = mn1;
            #pragma unroll
            for (int dt = 0; dt < 8; dt++) {
                o[rs][dt][0] *= a0; o[rs][dt][1] *= a0;
                o[rs][dt][2] *= a1; o[rs][dt][3] *= a1;
            }
        }

        // ---- GEMM2: O += PhVh + PhVl + PlVh (streamed P conversion) ----
        #pragma unroll
        for (int kpair = 0; kpair < 2; kpair++) {
            uint32_t ph2[2][2][4], pl2[2][2][4];
            #pragma unroll
            for (int rs = 0; rs < 2; rs++)
                #pragma unroll
                for (int i = 0; i < 2; i++) {
                    const int ntA = 4 * kpair + 2 * i, ntB = ntA + 1;
                    float p00 = s[rs][ntA][0], p01 = s[rs][ntA][1];
                    float p10 = s[rs][ntA][2], p11 = s[rs][ntA][3];
                    float p20 = s[rs][ntB][0], p21 = s[rs][ntB][1];
                    float p30 = s[rs][ntB][2], p31 = s[rs][ntB][3];
                    float h00 = tobf(p00), h01 = tobf(p01), h10 = tobf(p10), h11 = tobf(p11);
                    float h20 = tobf(p20), h21 = tobf(p21), h30 = tobf(p30), h31 = tobf(p31);
                    ph2[rs][i][0] = pack2(h00, h01); ph2[rs][i][1] = pack2(h10, h11);
                    ph2[rs][i][2] = pack2(h20, h21); ph2[rs][i][3] = pack2(h30, h31);
                    pl2[rs][i][0] = pack2(p00-h00, p01-h01); pl2[rs][i][1] = pack2(p10-h10, p11-h11);
                    pl2[rs][i][2] = pack2(p20-h20, p21-h21); pl2[rs][i][3] = pack2(p30-h30, p31-h31);
                }
            #pragma unroll
            for (int dt = 0; dt < 8; dt++) {
                uint32_t aoff = (uint32_t)((kpair * 32 + lane) * ROWB + dt * 16);
                uint32_t vh[4], vl[4];
                ldsm_x4_t(vh, sbase + OFF_VH + aoff);
                ldsm_x4_t(vl, sbase + OFF_VL + aoff);
                #pragma unroll
                for (int rs = 0; rs < 2; rs++) {
                    mma_bf16(o[rs][dt], ph2[rs][0], vh[0], vh[1]);
                    mma_bf16(o[rs][dt], ph2[rs][0], vl[0], vl[1]);
                    mma_bf16(o[rs][dt], pl2[rs][0], vh[0], vh[1]);
                    mma_bf16(o[rs][dt], ph2[rs][1], vh[2], vh[3]);
                    mma_bf16(o[rs][dt], ph2[rs][1], vl[2], vl[3]);
                    mma_bf16(o[rs][dt], pl2[rs][1], vh[2], vh[3]);
                }
            }
        }
    }

    // ---- normalize + write out ----
    #pragma unroll
    for (int rs = 0; rs < 2; rs++) {
        float inv0 = 1.f / l_i[rs][0], inv1 = 1.f / l_i[rs][1];
        float* op0 = Out + ((size_t)b * S_LEN + rowg[rs][0]) * DMODEL + h * HD;
        float* op1 = Out + ((size_t)b * S_LEN + rowg[rs][1]) * DMODEL + h * HD;
        #pragma unroll
        for (int dt = 0; dt < 8; dt++) {
            int c0 = dt * 8 + 2 * tig;
            *(float2*)(op0 + c0) = make_float2(o[rs][dt][0] * inv0, o[rs][dt][1] * inv0);
            *(float2*)(op1 + c0) = make_float2(o[rs][dt][2] * inv1, o[rs][dt][3] * inv1);
        }
    }
}

extern "C" void kernel_launch(void* const* d_in, const int* in_sizes, int n_in,
                              void* d_out, int out_size)
{
    const float* q = (const float*)d_in[0];
    const float* k = (const float*)d_in[1];
    const float* v = (const float*)d_in[2];
    const int* mask = (const int*)d_in[3];
    float* out = (float*)d_out;

    pack_mask<<<BATCH * S_LEN * S_LEN / 256, 256>>>(mask);

    cudaFuncSetAttribute(mha_mma, cudaFuncAttributeMaxDynamicSharedMemorySize, SMEM_TOTAL);
    dim3 grid(S_LEN / BM, NHEAD, BATCH);
    mha_mma<<<grid, NTH, SMEM_TOTAL>>>(q, k, v, out);
}